// round 14
// baseline (speedup 1.0000x reference)
#include <cuda_runtime.h>
#include <math.h>

#define NN   16384
#define HD   128
#define EE   524288
#define EDD  16
#define HID  256
#define EPSB 1e-5f
#define NEG  0.01f
#define CAP  128
#define RW   8

// ---------------- scratch (device globals; no allocation) ----------------
__device__ float g_P[NN*HD];
__device__ float g_y[NN*HD];
__device__ float g_M[HD*HD];
__device__ float g_u[HD], g_v[HD];
__device__ float g_c;
__device__ float g_a[NN], g_b[NN];
__device__ int   g_hist[NN];
__device__ int   g_fill[NN];
__device__ int   g_rowstart[NN+1];
__device__ int   g_cdst[EE];
__device__ float g_cs[EE];
__device__ float g_xsum[HD];
__device__ float g_h0[NN*HD];
__device__ float g_f1[NN*HID];
__device__ float g_h2[NN*HD];
__device__ float g_sum1[HD], g_sq1[HD], g_scale1[HD], g_shift1[HD];
__device__ float g_sum2[HD], g_sq2[HD], g_scale2[HD], g_shift2[HD];
__device__ int   g_notI64 = 0;

// ---------------- helpers ----------------
__device__ __forceinline__ int ld_idx(const long long* ei, int i) {
    return g_notI64 ? ((const int*)ei)[i] : (int)ei[i];
}
__device__ __forceinline__ float f2tf_f(float f) {
    unsigned u; asm("cvt.rna.tf32.f32 %0, %1;" : "=r"(u) : "f"(f));
    return __uint_as_float(u);
}
__device__ __forceinline__ void mma_tf32(float* c, const unsigned* a, const unsigned* b) {
    asm volatile(
        "mma.sync.aligned.m16n8k8.row.col.f32.tf32.tf32.f32 "
        "{%0,%1,%2,%3}, {%4,%5,%6,%7}, {%8,%9}, {%0,%1,%2,%3};\n"
        : "+f"(c[0]), "+f"(c[1]), "+f"(c[2]), "+f"(c[3])
        : "r"(a[0]), "r"(a[1]), "r"(a[2]), "r"(a[3]), "r"(b[0]), "r"(b[1]));
}
__device__ __forceinline__ int redux_addi(int v) {
    int r; asm volatile("redux.sync.add.s32 %0, %1, 0xffffffff;" : "=r"(r) : "r"(v)); return r;
}
__device__ __forceinline__ float wsum32(float v) {
#pragma unroll
    for (int o = 16; o; o >>= 1) v += __shfl_xor_sync(0xffffffffu, v, o);
    return v;
}

// ------------- fused init: zero scratch + dtype detect ----------------
__global__ void k_init(const long long* __restrict__ ei) {
    int i = blockIdx.x * blockDim.x + threadIdx.x;
    long long v = ei[i];
    if (v < 0 || v > (NN - 1)) g_notI64 = 1;
    if (i < NN) { g_hist[i] = 0; g_fill[i] = 0; }
    if (i < HD) {
        g_xsum[i] = 0.f;
        g_sum1[i] = 0.f; g_sq1[i] = 0.f;
        g_sum2[i] = 0.f; g_sq2[i] = 0.f;
    }
}

__global__ void k_hist(const long long* __restrict__ ei) {
    int e = blockIdx.x * blockDim.x + threadIdx.x;
    atomicAdd(&g_hist[ld_idx(ei, e)], 1);
}

// ------ u = Wq bk, v = Wk bq, c = bq.bk ------
__global__ __launch_bounds__(256) void k_uvc(
    const float* __restrict__ Wq, const float* __restrict__ bk,
    const float* __restrict__ Wk, const float* __restrict__ bq)
{
    int gw = blockIdx.x * 8 + (threadIdx.x >> 5);
    int lane = threadIdx.x & 31;
    int col = gw & 127;
    const float* W = (gw < 128) ? Wq : Wk;
    const float* b = (gw < 128) ? bk : bq;
    float4 wv = ((const float4*)(W + col * HD))[lane];
    float4 bv = ((const float4*)b)[lane];
    float s = wsum32(wv.x*bv.x + wv.y*bv.y + wv.z*bv.z + wv.w*bv.w);
    if (lane == 0) { if (gw < 128) g_u[col] = s; else g_v[col] = s; }
    if (gw == 0) {
        float4 q4 = ((const float4*)bq)[lane];
        float4 k4 = ((const float4*)bk)[lane];
        float c = wsum32(q4.x*k4.x + q4.y*k4.y + q4.z*k4.z + q4.w*k4.w);
        if (lane == 0) g_c = c;
    }
}

// ------ M = Wq @ Wk^T : warp per 4 outputs ------
__global__ __launch_bounds__(256) void k_mm(const float* __restrict__ Wq,
                                            const float* __restrict__ Wk) {
    int gw = blockIdx.x * 8 + (threadIdx.x >> 5);
    int lane = threadIdx.x & 31;
    int i = gw >> 5;
    int j0 = (gw & 31) * 4;
    float4 qv = ((const float4*)(Wq + i * HD))[lane];
    float p[4];
#pragma unroll
    for (int jj = 0; jj < 4; jj++) {
        float4 kv = ((const float4*)(Wk + (j0 + jj) * HD))[lane];
        p[jj] = qv.x*kv.x + qv.y*kv.y + qv.z*kv.z + qv.w*kv.w;
    }
#pragma unroll
    for (int o = 16; o; o >>= 1) {
#pragma unroll
        for (int jj = 0; jj < 4; jj++)
            p[jj] += __shfl_xor_sync(0xffffffffu, p[jj], o);
    }
    if (lane == 0) {
        g_M[i * HD + j0]     = p[0];
        g_M[i * HD + j0 + 1] = p[1];
        g_M[i * HD + j0 + 2] = p[2];
        g_M[i * HD + j0 + 3] = p[3];
    }
}

// ---------------- a[i] = x_i . u ; b[i] = x_i . v ----------------
__global__ __launch_bounds__(256) void k_ab(const float* __restrict__ x) {
    int w = threadIdx.x >> 5, lane = threadIdx.x & 31;
    int row = blockIdx.x * 8 + w;
    float4 xr = ((const float4*)x)[row * 32 + lane];
    float4 uu = ((const float4*)g_u)[lane];
    float4 vv = ((const float4*)g_v)[lane];
    float pa = xr.x*uu.x + xr.y*uu.y + xr.z*uu.z + xr.w*uu.w;
    float pb = xr.x*vv.x + xr.y*vv.y + xr.z*vv.z + xr.w*vv.w;
#pragma unroll
    for (int o = 16; o; o >>= 1) {
        pa += __shfl_xor_sync(0xffffffffu, pa, o);
        pb += __shfl_xor_sync(0xffffffffu, pb, o);
    }
    if (lane == 0) { g_a[row] = pa; g_b[row] = pb; }
}

// ------- P = x @ M tf32 GEMM, 3-term split, 64x128 tile, DOUBLE-BUFFERED ---
__global__ __launch_bounds__(256) void k_pgemm(const float* __restrict__ x)
{
    __shared__ float Ah[2][16][68], Al[2][16][68];
    __shared__ float Bh[2][16][132], Bl[2][16][132];
    int t = threadIdx.x;
    int row0 = blockIdx.y * 64;
    int wid = t >> 5, lane = t & 31;
    int wm = (wid >> 2) * 32, wn = (wid & 3) * 32;
    int lr = lane & 3, lg = lane >> 2;
    float acc[2][4][4] = {};
    int ar = t >> 2, ak4 = (t & 3) * 4;
    int i0 = t * 2, i1 = t * 2 + 1;
    int bk0 = i0 >> 5, bn0 = (i0 & 31) * 4;
    int bk1 = i1 >> 5, bn1 = (i1 & 31) * 4;

    {
        float4 av = *(const float4*)&x[(row0 + ar) * HD + ak4];
        float hx = f2tf_f(av.x), hy = f2tf_f(av.y), hz = f2tf_f(av.z), hw = f2tf_f(av.w);
        Ah[0][ak4+0][ar] = hx; Al[0][ak4+0][ar] = f2tf_f(av.x - hx);
        Ah[0][ak4+1][ar] = hy; Al[0][ak4+1][ar] = f2tf_f(av.y - hy);
        Ah[0][ak4+2][ar] = hz; Al[0][ak4+2][ar] = f2tf_f(av.z - hz);
        Ah[0][ak4+3][ar] = hw; Al[0][ak4+3][ar] = f2tf_f(av.w - hw);
        float4 bv0 = *(const float4*)&g_M[bk0 * HD + bn0];
        float4 bv1 = *(const float4*)&g_M[bk1 * HD + bn1];
        float4 h, l;
        h.x = f2tf_f(bv0.x); l.x = f2tf_f(bv0.x - h.x);
        h.y = f2tf_f(bv0.y); l.y = f2tf_f(bv0.y - h.y);
        h.z = f2tf_f(bv0.z); l.z = f2tf_f(bv0.z - h.z);
        h.w = f2tf_f(bv0.w); l.w = f2tf_f(bv0.w - h.w);
        *(float4*)&Bh[0][bk0][bn0] = h;
        *(float4*)&Bl[0][bk0][bn0] = l;
        h.x = f2tf_f(bv1.x); l.x = f2tf_f(bv1.x - h.x);
        h.y = f2tf_f(bv1.y); l.y = f2tf_f(bv1.y - h.y);
        h.z = f2tf_f(bv1.z); l.z = f2tf_f(bv1.z - h.z);
        h.w = f2tf_f(bv1.w); l.w = f2tf_f(bv1.w - h.w);
        *(float4*)&Bh[0][bk1][bn1] = h;
        *(float4*)&Bl[0][bk1][bn1] = l;
    }
    __syncthreads();

    for (int it = 0; it < HD / 16; it++) {
        int cur = it & 1, nxt = cur ^ 1;
        float4 aN, bN0, bN1;
        bool more = (it + 1) < HD / 16;
        if (more) {
            int kn = (it + 1) * 16;
            aN  = *(const float4*)&x[(row0 + ar) * HD + kn + ak4];
            bN0 = *(const float4*)&g_M[(kn + bk0) * HD + bn0];
            bN1 = *(const float4*)&g_M[(kn + bk1) * HD + bn1];
        }
#pragma unroll
        for (int ks = 0; ks < 16; ks += 8) {
            unsigned ah[2][4], al[2][4];
#pragma unroll
            for (int mt = 0; mt < 2; mt++) {
                int m = wm + mt * 16 + lg;
                ah[mt][0] = __float_as_uint(Ah[cur][ks + lr][m]);
                ah[mt][1] = __float_as_uint(Ah[cur][ks + lr][m + 8]);
                ah[mt][2] = __float_as_uint(Ah[cur][ks + 4 + lr][m]);
                ah[mt][3] = __float_as_uint(Ah[cur][ks + 4 + lr][m + 8]);
                al[mt][0] = __float_as_uint(Al[cur][ks + lr][m]);
                al[mt][1] = __float_as_uint(Al[cur][ks + lr][m + 8]);
                al[mt][2] = __float_as_uint(Al[cur][ks + 4 + lr][m]);
                al[mt][3] = __float_as_uint(Al[cur][ks + 4 + lr][m + 8]);
            }
#pragma unroll
            for (int nt = 0; nt < 4; nt++) {
                int n = wn + nt * 8 + lg;
                unsigned bh[2], bl[2];
                bh[0] = __float_as_uint(Bh[cur][ks + lr][n]);
                bh[1] = __float_as_uint(Bh[cur][ks + 4 + lr][n]);
                bl[0] = __float_as_uint(Bl[cur][ks + lr][n]);
                bl[1] = __float_as_uint(Bl[cur][ks + 4 + lr][n]);
#pragma unroll
                for (int mt = 0; mt < 2; mt++) {
                    mma_tf32(acc[mt][nt], ah[mt], bl);
                    mma_tf32(acc[mt][nt], al[mt], bh);
                    mma_tf32(acc[mt][nt], ah[mt], bh);
                }
            }
        }
        if (more) {
            float hx = f2tf_f(aN.x), hy = f2tf_f(aN.y), hz = f2tf_f(aN.z), hw = f2tf_f(aN.w);
            Ah[nxt][ak4+0][ar] = hx; Al[nxt][ak4+0][ar] = f2tf_f(aN.x - hx);
            Ah[nxt][ak4+1][ar] = hy; Al[nxt][ak4+1][ar] = f2tf_f(aN.y - hy);
            Ah[nxt][ak4+2][ar] = hz; Al[nxt][ak4+2][ar] = f2tf_f(aN.z - hz);
            Ah[nxt][ak4+3][ar] = hw; Al[nxt][ak4+3][ar] = f2tf_f(aN.w - hw);
            float4 h, l;
            h.x = f2tf_f(bN0.x); l.x = f2tf_f(bN0.x - h.x);
            h.y = f2tf_f(bN0.y); l.y = f2tf_f(bN0.y - h.y);
            h.z = f2tf_f(bN0.z); l.z = f2tf_f(bN0.z - h.z);
            h.w = f2tf_f(bN0.w); l.w = f2tf_f(bN0.w - h.w);
            *(float4*)&Bh[nxt][bk0][bn0] = h;
            *(float4*)&Bl[nxt][bk0][bn0] = l;
            h.x = f2tf_f(bN1.x); l.x = f2tf_f(bN1.x - h.x);
            h.y = f2tf_f(bN1.y); l.y = f2tf_f(bN1.y - h.y);
            h.z = f2tf_f(bN1.z); l.z = f2tf_f(bN1.z - h.z);
            h.w = f2tf_f(bN1.w); l.w = f2tf_f(bN1.w - h.w);
            *(float4*)&Bh[nxt][bk1][bn1] = h;
            *(float4*)&Bl[nxt][bk1][bn1] = l;
        }
        __syncthreads();
    }
#pragma unroll
    for (int mt = 0; mt < 2; mt++)
#pragma unroll
        for (int nt = 0; nt < 4; nt++) {
            int r = row0 + wm + mt * 16 + lg;
            int c = wn + nt * 8 + lr * 2;
#pragma unroll
            for (int h = 0; h < 2; h++) {
                int rr = r + h * 8;
                g_P[rr * HD + c]     = acc[mt][nt][h * 2];
                g_P[rr * HD + c + 1] = acc[mt][nt][h * 2 + 1];
            }
        }
}

// ------- tf32 tensor GEMM: 64x128 tile, DOUBLE-BUFFERED --------------------
// epi: 1 relu, 2 residual*BN, 3 plain residual
__global__ __launch_bounds__(256) void k_mma(
    const float* __restrict__ A, const float* __restrict__ B,
    const float* __restrict__ bias, float* __restrict__ C,
    int Ncols, int K,
    const float* __restrict__ sA, const float* __restrict__ hA,
    int epi, const float* __restrict__ res,
    const float* __restrict__ rs, const float* __restrict__ rh)
{
    __shared__ float As[2][16][68];
    __shared__ float Bs[2][16][132];
    int t = threadIdx.x;
    int row0 = blockIdx.y * 64;
    int col0 = blockIdx.x * 128;
    int wid = t >> 5, lane = t & 31;
    int wm = (wid >> 2) * 32, wn = (wid & 3) * 32;
    int lr = lane & 3, lg = lane >> 2;
    float acc[2][4][4] = {};
    int am_ = t >> 2, ak4 = (t & 3) * 4;
    int i0 = t * 2, i1 = t * 2 + 1;
    int bk0 = i0 >> 5, bn0 = (i0 & 31) * 4;
    int bk1 = i1 >> 5, bn1 = (i1 & 31) * 4;

    {
        float4 av = *(const float4*)&A[(row0 + am_) * K + ak4];
        if (sA) {
            av.x = av.x * sA[ak4  ] + hA[ak4  ];
            av.y = av.y * sA[ak4+1] + hA[ak4+1];
            av.z = av.z * sA[ak4+2] + hA[ak4+2];
            av.w = av.w * sA[ak4+3] + hA[ak4+3];
        }
        As[0][ak4  ][am_] = f2tf_f(av.x);
        As[0][ak4+1][am_] = f2tf_f(av.y);
        As[0][ak4+2][am_] = f2tf_f(av.z);
        As[0][ak4+3][am_] = f2tf_f(av.w);
        float4 bv0 = *(const float4*)&B[bk0 * Ncols + col0 + bn0];
        float4 bv1 = *(const float4*)&B[bk1 * Ncols + col0 + bn1];
        float4 bw;
        bw.x = f2tf_f(bv0.x); bw.y = f2tf_f(bv0.y);
        bw.z = f2tf_f(bv0.z); bw.w = f2tf_f(bv0.w);
        *(float4*)&Bs[0][bk0][bn0] = bw;
        bw.x = f2tf_f(bv1.x); bw.y = f2tf_f(bv1.y);
        bw.z = f2tf_f(bv1.z); bw.w = f2tf_f(bv1.w);
        *(float4*)&Bs[0][bk1][bn1] = bw;
    }
    __syncthreads();

    int T = K / 16;
    for (int it = 0; it < T; it++) {
        int cur = it & 1, nxt = cur ^ 1;
        float4 aN, bN0, bN1;
        bool more = (it + 1) < T;
        int kn = (it + 1) * 16;
        if (more) {
            aN  = *(const float4*)&A[(row0 + am_) * K + kn + ak4];
            bN0 = *(const float4*)&B[(kn + bk0) * Ncols + col0 + bn0];
            bN1 = *(const float4*)&B[(kn + bk1) * Ncols + col0 + bn1];
        }
#pragma unroll
        for (int ks = 0; ks < 16; ks += 8) {
            unsigned a[2][4], b[4][2];
#pragma unroll
            for (int mt = 0; mt < 2; mt++) {
                int m = wm + mt * 16 + lg;
                a[mt][0] = __float_as_uint(As[cur][ks + lr][m]);
                a[mt][1] = __float_as_uint(As[cur][ks + lr][m + 8]);
                a[mt][2] = __float_as_uint(As[cur][ks + 4 + lr][m]);
                a[mt][3] = __float_as_uint(As[cur][ks + 4 + lr][m + 8]);
            }
#pragma unroll
            for (int nt = 0; nt < 4; nt++) {
                int n = wn + nt * 8 + lg;
                b[nt][0] = __float_as_uint(Bs[cur][ks + lr][n]);
                b[nt][1] = __float_as_uint(Bs[cur][ks + 4 + lr][n]);
            }
#pragma unroll
            for (int mt = 0; mt < 2; mt++)
#pragma unroll
                for (int nt = 0; nt < 4; nt++)
                    mma_tf32(acc[mt][nt], a[mt], b[nt]);
        }
        if (more) {
            if (sA) {
                aN.x = aN.x * sA[kn+ak4  ] + hA[kn+ak4  ];
                aN.y = aN.y * sA[kn+ak4+1] + hA[kn+ak4+1];
                aN.z = aN.z * sA[kn+ak4+2] + hA[kn+ak4+2];
                aN.w = aN.w * sA[kn+ak4+3] + hA[kn+ak4+3];
            }
            As[nxt][ak4  ][am_] = f2tf_f(aN.x);
            As[nxt][ak4+1][am_] = f2tf_f(aN.y);
            As[nxt][ak4+2][am_] = f2tf_f(aN.z);
            As[nxt][ak4+3][am_] = f2tf_f(aN.w);
            float4 bw;
            bw.x = f2tf_f(bN0.x); bw.y = f2tf_f(bN0.y);
            bw.z = f2tf_f(bN0.z); bw.w = f2tf_f(bN0.w);
            *(float4*)&Bs[nxt][bk0][bn0] = bw;
            bw.x = f2tf_f(bN1.x); bw.y = f2tf_f(bN1.y);
            bw.z = f2tf_f(bN1.z); bw.w = f2tf_f(bN1.w);
            *(float4*)&Bs[nxt][bk1][bn1] = bw;
        }
        __syncthreads();
    }
#pragma unroll
    for (int mt = 0; mt < 2; mt++) {
#pragma unroll
        for (int nt = 0; nt < 4; nt++) {
            int r = row0 + wm + mt * 16 + lg;
            int c = col0 + wn + nt * 8 + lr * 2;
#pragma unroll
            for (int h = 0; h < 2; h++) {
                int rr = r + h * 8;
                float v0 = acc[mt][nt][h * 2]     + bias[c];
                float v1 = acc[mt][nt][h * 2 + 1] + bias[c + 1];
                if (epi == 1) { v0 = fmaxf(v0, 0.f); v1 = fmaxf(v1, 0.f); }
                else if (epi == 2) {
                    v0 += res[rr * HD + c]     * rs[c]     + rh[c];
                    v1 += res[rr * HD + c + 1] * rs[c + 1] + rh[c + 1];
                } else if (epi == 3) {
                    v0 += res[rr * HD + c];
                    v1 += res[rr * HD + c + 1];
                }
                C[rr * Ncols + c]     = v0;
                C[rr * Ncols + c + 1] = v1;
            }
        }
    }
}

// ---------------- exclusive scan over 16384 counts ----------------
__global__ void k_scan() {
    __shared__ int ps[1024];
    int t = threadIdx.x;
    int base = t * 16;
    int loc[16]; int s = 0;
#pragma unroll
    for (int i = 0; i < 16; i++) { loc[i] = g_hist[base + i]; s += loc[i]; }
    ps[t] = s;
    __syncthreads();
    for (int off = 1; off < 1024; off <<= 1) {
        int v = (t >= off) ? ps[t - off] : 0;
        __syncthreads();
        ps[t] += v;
        __syncthreads();
    }
    int run = ps[t] - s;
#pragma unroll
    for (int i = 0; i < 16; i++) { g_rowstart[base + i] = run; run += loc[i]; }
    if (t == 1023) g_rowstart[NN] = run;
}

// ---------------- column sum of x ----------------
__global__ void k_xsum(const float* __restrict__ x) {
    int c = threadIdx.x;
    int b = blockIdx.x;
    float s = 0.f;
    for (int r = b * 128; r < (b + 1) * 128; r++) s += x[r * HD + c];
    atomicAdd(&g_xsum[c], s);
}

// ------- edge bias + b[dst] + scatter into CSR ----------------
__global__ void k_scatter(const float* __restrict__ ea, const float* __restrict__ We,
                          const float* __restrict__ be, const long long* __restrict__ ei)
{
    int e = blockIdx.x * blockDim.x + threadIdx.x;
    const float4* a4 = (const float4*)(ea + (size_t)e * EDD);
    float s = be[0];
#pragma unroll
    for (int i = 0; i < 4; i++) {
        float4 v = a4[i];
        s += v.x * We[i*4] + v.y * We[i*4+1] + v.z * We[i*4+2] + v.w * We[i*4+3];
    }
    int src = ld_idx(ei, e);
    int dst = ld_idx(ei, EE + e);
    int pos = g_rowstart[src] + atomicAdd(&g_fill[src], 1);
    g_cdst[pos] = dst;
    g_cs[pos]   = s + g_b[dst];
}

// ------- per-row fused score+softmax+x-gather -> y = attn @ x -------------
__global__ __launch_bounds__(256) void k_row(const float* __restrict__ x) {
    __shared__ int   sd[RW][CAP];
    __shared__ float ss[RW][CAP];
    __shared__ int   sf[RW][CAP];
    int t = threadIdx.x;
    int w = t >> 5, lane = t & 31;
    int row = blockIdx.x * RW + w;
    int start = g_rowstart[row], end = g_rowstart[row + 1];
    int k = end - start;
    const float4* X4 = (const float4*)x;
    float4 q = ((const float4*)g_P)[row * 32 + lane];
    float arow = g_a[row] + g_c;
    float4 acc;
    float invden;

    if (k <= CAP) {
        for (int i = lane; i < k; i += 32) { sd[w][i] = g_cdst[start + i]; ss[w][i] = g_cs[start + i]; }
        __syncwarp();
        bool myDup = false;
        for (int i = lane; i < k; i += 32) {
            int d = sd[w][i]; int f = 0;
            while (sd[w][f] != d) f++;
            sf[w][i] = f;
            if (f != i) myDup = true;
        }
        bool anyDup = __any_sync(0xffffffffu, myDup);
        __syncwarp();

        float sumExp = 0.f;
        float4 vs = ((const float4*)g_xsum)[lane];
        float4 a0 = vs, a1 = make_float4(0,0,0,0), a2 = a1, a3 = a1;

        if (!anyDup) {
            // 8 cells/iter, 8 x-gathers in flight, 8 interleaved shuffle chains
            for (int i0 = 0; i0 < k; i0 += 8) {
                int n = k - i0; if (n > 8) n = 8;
                int dd[8];
#pragma unroll
                for (int j = 0; j < 8; j++) dd[j] = sd[w][(j < n) ? i0 + j : k - 1];
                float4 xv[8];
#pragma unroll
                for (int j = 0; j < 8; j++) xv[j] = X4[dd[j] * 32 + lane];
                float p[8];
#pragma unroll
                for (int j = 0; j < 8; j++)
                    p[j] = q.x*xv[j].x + q.y*xv[j].y + q.z*xv[j].z + q.w*xv[j].w;
#pragma unroll
                for (int o = 16; o; o >>= 1) {
#pragma unroll
                    for (int j = 0; j < 8; j++)
                        p[j] += __shfl_xor_sync(0xffffffffu, p[j], o);
                }
#pragma unroll
                for (int j = 0; j < 8; j++) {
                    float wj = 0.f;
                    if (j < n) {
                        float s = p[j] + ss[w][i0 + j] + arow;
                        s = (s >= 0.f) ? s : NEG * s;
                        float e = __expf(s);
                        sumExp += e;
                        wj = e - 1.f;
                    }
                    float4* a = (j & 2) ? ((j & 1) ? &a3 : &a2) : ((j & 1) ? &a1 : &a0);
                    a->x += wj * xv[j].x; a->y += wj * xv[j].y;
                    a->z += wj * xv[j].z; a->w += wj * xv[j].w;
                }
            }
            invden = 1.f / (sumExp + (float)(NN - k));
        } else {
            for (int i0 = 0; i0 < k; i0 += 4) {
                int n = k - i0; if (n > 4) n = 4;
                int d0 = sd[w][i0];
                int d1 = sd[w][i0 + (n > 1 ? 1 : 0)];
                int d2 = sd[w][i0 + (n > 2 ? 2 : 0)];
                int d3 = sd[w][i0 + (n > 3 ? 3 : 0)];
                float4 x0 = X4[d0 * 32 + lane];
                float4 x1 = X4[d1 * 32 + lane];
                float4 x2 = X4[d2 * 32 + lane];
                float4 x3 = X4[d3 * 32 + lane];
                float p0 = q.x*x0.x + q.y*x0.y + q.z*x0.z + q.w*x0.w;
                float p1 = q.x*x1.x + q.y*x1.y + q.z*x1.z + q.w*x1.w;
                float p2 = q.x*x2.x + q.y*x2.y + q.z*x2.z + q.w*x2.w;
                float p3 = q.x*x3.x + q.y*x3.y + q.z*x3.z + q.w*x3.w;
#pragma unroll
                for (int o = 16; o; o >>= 1) {
                    p0 += __shfl_xor_sync(0xffffffffu, p0, o);
                    p1 += __shfl_xor_sync(0xffffffffu, p1, o);
                    p2 += __shfl_xor_sync(0xffffffffu, p2, o);
                    p3 += __shfl_xor_sync(0xffffffffu, p3, o);
                }
                if (lane == 0) {
                    float s0 = p0 + ss[w][i0] + arow; ss[w][i0] = (s0>=0.f)?s0:NEG*s0;
                    if (n > 1) { float s1 = p1 + ss[w][i0+1] + arow; ss[w][i0+1] = (s1>=0.f)?s1:NEG*s1; }
                    if (n > 2) { float s2 = p2 + ss[w][i0+2] + arow; ss[w][i0+2] = (s2>=0.f)?s2:NEG*s2; }
                    if (n > 3) { float s3 = p3 + ss[w][i0+3] + arow; ss[w][i0+3] = (s3>=0.f)?s3:NEG*s3; }
                }
            }
            __syncwarp();
            for (int i = lane; i < k; i += 32)
                if (sf[w][i] != i) atomicAdd(&ss[w][sf[w][i]], ss[w][i]);
            __syncwarp();
            int cnt = 0;
            for (int i = lane; i < k; i += 32) {
                float wv = 0.f;
                if (sf[w][i] == i) {
                    float e1 = __expf(ss[w][i]);
                    sumExp += e1;
                    wv = e1 - 1.f;
                    cnt++;
                }
                ss[w][i] = wv;
            }
            __syncwarp();
            cnt = redux_addi(cnt);
            sumExp = wsum32(sumExp);
            for (int i = 0; i + 4 <= k; i += 4) {
                float w0 = ss[w][i], w1 = ss[w][i+1], w2 = ss[w][i+2], w3 = ss[w][i+3];
                float4 v0 = X4[sd[w][i]   * 32 + lane];
                float4 v1 = X4[sd[w][i+1] * 32 + lane];
                float4 v2 = X4[sd[w][i+2] * 32 + lane];
                float4 v3 = X4[sd[w][i+3] * 32 + lane];
                a0.x += w0*v0.x; a0.y += w0*v0.y; a0.z += w0*v0.z; a0.w += w0*v0.w;
                a1.x += w1*v1.x; a1.y += w1*v1.y; a1.z += w1*v1.z; a1.w += w1*v1.w;
                a2.x += w2*v2.x; a2.y += w2*v2.y; a2.z += w2*v2.z; a2.w += w2*v2.w;
                a3.x += w3*v3.x; a3.y += w3*v3.y; a3.z += w3*v3.z; a3.w += w3*v3.w;
            }
            for (int i = k & ~3; i < k; i++) {
                float wv = ss[w][i];
                float4 v = X4[sd[w][i] * 32 + lane];
                a0.x += wv*v.x; a0.y += wv*v.y; a0.z += wv*v.z; a0.w += wv*v.w;
            }
            invden = 1.f / (sumExp + (float)(NN - cnt));
        }
        acc.x = (a0.x + a1.x) + (a2.x + a3.x);
        acc.y = (a0.y + a1.y) + (a2.y + a3.y);
        acc.z = (a0.z + a1.z) + (a2.z + a3.z);
        acc.w = (a0.w + a1.w) + (a2.w + a3.w);
    } else {
        float sumExp = 0.f; int cnt = 0;
        float4 vs = ((const float4*)g_xsum)[lane];
        acc.x = vs.x; acc.y = vs.y; acc.z = vs.z; acc.w = vs.w;
        for (int i = 0; i < k; i++) {
            int d = g_cdst[start + i];
            bool first = true;
            for (int j = 0; j < i; j++) if (g_cdst[start + j] == d) { first = false; break; }
            if (!first) continue;
            float4 xv = X4[d * 32 + lane];
            float p = wsum32(q.x*xv.x + q.y*xv.y + q.z*xv.z + q.w*xv.w);
            float v = 0.f;
            for (int j = i; j < k; j++)
                if (g_cdst[start + j] == d) {
                    float s = p + g_cs[start + j] + arow;
                    v += (s >= 0.f) ? s : NEG * s;
                }
            float e1 = __expf(v);
            sumExp += e1;
            float wv = e1 - 1.f;
            cnt++;
            acc.x += wv*xv.x; acc.y += wv*xv.y; acc.z += wv*xv.z; acc.w += wv*xv.w;
        }
        invden = 1.f / (sumExp + (float)(NN - cnt));
    }

    float4 o;
    o.x = acc.x * invden;
    o.y = acc.y * invden;
    o.z = acc.z * invden;
    o.w = acc.w * invden;
    ((float4*)g_y)[row * 32 + lane] = o;
}

// ---------------- batchnorm column stats ----------------
__global__ void k_stats(const float* __restrict__ src, float* __restrict__ osum, float* __restrict__ osq) {
    __shared__ float sh1[128], sh2[128];
    int t = threadIdx.x;
    int c = t & 127, half = t >> 7;
    int r0 = blockIdx.x * 128 + half;
    float s = 0.f, q = 0.f;
    for (int i = 0; i < 64; i++) {
        float v = src[(r0 + 2 * i) * HD + c];
        s += v; q += v * v;
    }
    if (half) { sh1[c] = s; sh2[c] = q; }
    __syncthreads();
    if (!half) {
        atomicAdd(&osum[c], s + sh1[c]);
        atomicAdd(&osq[c],  q + sh2[c]);
    }
}

__global__ void k_finalize(const float* __restrict__ sum, const float* __restrict__ sq,
                           const float* __restrict__ g, const float* __restrict__ b,
                           float* __restrict__ sc, float* __restrict__ sh) {
    int c = threadIdx.x;
    float mean = sum[c] * (1.f / NN);
    float var  = sq[c] * (1.f / NN) - mean * mean;
    float s = g[c] * rsqrtf(var + EPSB);
    sc[c] = s;
    sh[c] = b[c] - mean * s;
}

// ---------------- final BN2 apply ----------------
__global__ void k_out(float* __restrict__ out) {
    int i = blockIdx.x * blockDim.x + threadIdx.x;
    float4 v = ((const float4*)g_h2)[i];
    int c = (i & 31) * 4;
    float4 o;
    o.x = v.x * g_scale2[c  ] + g_shift2[c  ];
    o.y = v.y * g_scale2[c+1] + g_shift2[c+1];
    o.z = v.z * g_scale2[c+2] + g_shift2[c+2];
    o.w = v.w * g_scale2[c+3] + g_shift2[c+3];
    ((float4*)out)[i] = o;
}

// ---------------- host ----------------
extern "C" void kernel_launch(void* const* d_in, const int* in_sizes, int n_in,
                              void* d_out, int out_size) {
    const float*     x   = (const float*)d_in[0];
    const long long* ei  = (const long long*)d_in[1];
    const float*     ea  = (const float*)d_in[2];
    const float*     Wq  = (const float*)d_in[3];  const float* bq  = (const float*)d_in[4];
    const float*     Wk  = (const float*)d_in[5];  const float* bk  = (const float*)d_in[6];
    const float*     Wv  = (const float*)d_in[7];  const float* bv  = (const float*)d_in[8];
    const float*     We  = (const float*)d_in[9];  const float* be  = (const float*)d_in[10];
    const float*     g1  = (const float*)d_in[11]; const float* be1 = (const float*)d_in[12];
    const float*     W1  = (const float*)d_in[13]; const float* b1  = (const float*)d_in[14];
    const float*     W2  = (const float*)d_in[15]; const float* b2  = (const float*)d_in[16];
    const float*     g2  = (const float*)d_in[17]; const float* be2 = (const float*)d_in[18];

    float *py, *ph0, *pf1, *ph2;
    float *ps1, *pq1, *psc1, *psh1, *ps2, *pq2, *psc2, *psh2;
    cudaGetSymbolAddress((void**)&py,   g_y);
    cudaGetSymbolAddress((void**)&ph0,  g_h0);
    cudaGetSymbolAddress((void**)&pf1,  g_f1);
    cudaGetSymbolAddress((void**)&ph2,  g_h2);
    cudaGetSymbolAddress((void**)&ps1,  g_sum1);
    cudaGetSymbolAddress((void**)&pq1,  g_sq1);
    cudaGetSymbolAddress((void**)&psc1, g_scale1);
    cudaGetSymbolAddress((void**)&psh1, g_shift1);
    cudaGetSymbolAddress((void**)&ps2,  g_sum2);
    cudaGetSymbolAddress((void**)&pq2,  g_sq2);
    cudaGetSymbolAddress((void**)&psc2, g_scale2);
    cudaGetSymbolAddress((void**)&psh2, g_shift2);

    static cudaStream_t s2 = nullptr;
    static cudaEvent_t evFork = nullptr, evJoin = nullptr;
    if (s2 == nullptr) {
        cudaStreamCreateWithFlags(&s2, cudaStreamNonBlocking);
        cudaEventCreateWithFlags(&evFork, cudaEventDisableTiming);
        cudaEventCreateWithFlags(&evJoin, cudaEventDisableTiming);
    }

    cudaEventRecord(evFork, 0);
    cudaStreamWaitEvent(s2, evFork, 0);

    k_uvc<<<32, 256, 0, s2>>>(Wq, bk, Wk, bq);
    k_ab<<<NN / 8, 256, 0, s2>>>(x);
    k_mm<<<512, 256, 0, s2>>>(Wq, Wk);
    dim3 gP(1, NN / 64);
    k_pgemm<<<gP, 256, 0, s2>>>(x);
    k_xsum<<<128, 128, 0, s2>>>(x);
    cudaEventRecord(evJoin, s2);

    k_init<<<EE / 256, 256>>>(ei);
    k_hist<<<EE / 256, 256>>>(ei);
    k_scan<<<1, 1024>>>();

    cudaStreamWaitEvent(0, evJoin, 0);

    k_scatter<<<EE / 256, 256>>>(ea, We, be, ei);
    k_row<<<NN / RW, 256>>>(x);

    dim3 gY(HD / 128, NN / 64);
    k_mma<<<gY, 256>>>(py, Wv, bv, ph0, HD, HD, nullptr, nullptr, 3, x, nullptr, nullptr);

    k_stats<<<128, 256>>>(ph0, ps1, pq1);
    k_finalize<<<1, 128>>>(ps1, pq1, g1, be1, psc1, psh1);

    dim3 gF1(HID / 128, NN / 64);
    k_mma<<<gF1, 256>>>(ph0, W1, b1, pf1, HID, HD, psc1, psh1, 1, nullptr, nullptr, nullptr);
    dim3 gF2(HD / 128, NN / 64);
    k_mma<<<gF2, 256>>>(pf1, W2, b2, ph2, HD, HID, nullptr, nullptr, 2, ph0, psc1, psh1);

    k_stats<<<128, 256>>>(ph2, ps2, pq2);
    k_finalize<<<1, 128>>>(ps2, pq2, g2, be2, psc2, psh2);
    k_out<<<(NN * HD / 4) / 256, 256>>>((float*)d_out);
}

// round 15
// speedup vs baseline: 1.5227x; 1.5227x over previous
#include <cuda_runtime.h>
#include <math.h>

#define NN   16384
#define HD   128
#define EE   524288
#define EDD  16
#define HID  256
#define EPSB 1e-5f
#define NEG  0.01f
#define CAP  128
#define RW   8

// ---------------- scratch (device globals; no allocation) ----------------
__device__ float g_P[NN*HD];
__device__ float g_y[NN*HD];
__device__ float g_M[HD*HD];
__device__ float g_u[HD], g_v[HD];
__device__ float g_c;
__device__ float g_a[NN], g_b[NN];
__device__ int   g_hist[NN];
__device__ int   g_fill[NN];
__device__ int   g_rowstart[NN+1];
__device__ int   g_cdst[EE];
__device__ float g_cs[EE];
__device__ float g_xsum[HD];
__device__ float g_h0[NN*HD];
__device__ float g_f1[NN*HID];
__device__ float g_h2[NN*HD];
__device__ float g_sum1[HD], g_sq1[HD], g_scale1[HD], g_shift1[HD];
__device__ float g_sum2[HD], g_sq2[HD], g_scale2[HD], g_shift2[HD];
__device__ int   g_notI64 = 0;

// ---------------- helpers ----------------
__device__ __forceinline__ int ld_idx(const long long* ei, int i) {
    return g_notI64 ? ((const int*)ei)[i] : (int)ei[i];
}
__device__ __forceinline__ float f2tf_f(float f) {
    unsigned u; asm("cvt.rna.tf32.f32 %0, %1;" : "=r"(u) : "f"(f));
    return __uint_as_float(u);
}
__device__ __forceinline__ void mma_tf32(float* c, const unsigned* a, const unsigned* b) {
    asm volatile(
        "mma.sync.aligned.m16n8k8.row.col.f32.tf32.tf32.f32 "
        "{%0,%1,%2,%3}, {%4,%5,%6,%7}, {%8,%9}, {%0,%1,%2,%3};\n"
        : "+f"(c[0]), "+f"(c[1]), "+f"(c[2]), "+f"(c[3])
        : "r"(a[0]), "r"(a[1]), "r"(a[2]), "r"(a[3]), "r"(b[0]), "r"(b[1]));
}
__device__ __forceinline__ int redux_addi(int v) {
    int r; asm volatile("redux.sync.add.s32 %0, %1, 0xffffffff;" : "=r"(r) : "r"(v)); return r;
}
__device__ __forceinline__ float wsum32(float v) {
#pragma unroll
    for (int o = 16; o; o >>= 1) v += __shfl_xor_sync(0xffffffffu, v, o);
    return v;
}

// ------------- fused init: zero scratch + dtype detect ----------------
__global__ void k_init(const long long* __restrict__ ei) {
    int i = blockIdx.x * blockDim.x + threadIdx.x;
    long long v = ei[i];
    if (v < 0 || v > (NN - 1)) g_notI64 = 1;
    if (i < NN) { g_hist[i] = 0; g_fill[i] = 0; }
    if (i < HD) {
        g_xsum[i] = 0.f;
        g_sum1[i] = 0.f; g_sq1[i] = 0.f;
        g_sum2[i] = 0.f; g_sq2[i] = 0.f;
    }
}

__global__ void k_hist(const long long* __restrict__ ei) {
    int e = blockIdx.x * blockDim.x + threadIdx.x;
    atomicAdd(&g_hist[ld_idx(ei, e)], 1);
}

// ------ u = Wq bk, v = Wk bq, c = bq.bk ------
__global__ __launch_bounds__(256) void k_uvc(
    const float* __restrict__ Wq, const float* __restrict__ bk,
    const float* __restrict__ Wk, const float* __restrict__ bq)
{
    int gw = blockIdx.x * 8 + (threadIdx.x >> 5);
    int lane = threadIdx.x & 31;
    int col = gw & 127;
    const float* W = (gw < 128) ? Wq : Wk;
    const float* b = (gw < 128) ? bk : bq;
    float4 wv = ((const float4*)(W + col * HD))[lane];
    float4 bv = ((const float4*)b)[lane];
    float s = wsum32(wv.x*bv.x + wv.y*bv.y + wv.z*bv.z + wv.w*bv.w);
    if (lane == 0) { if (gw < 128) g_u[col] = s; else g_v[col] = s; }
    if (gw == 0) {
        float4 q4 = ((const float4*)bq)[lane];
        float4 k4 = ((const float4*)bk)[lane];
        float c = wsum32(q4.x*k4.x + q4.y*k4.y + q4.z*k4.z + q4.w*k4.w);
        if (lane == 0) g_c = c;
    }
}

// ------ M = Wq @ Wk^T : warp per 4 outputs ------
__global__ __launch_bounds__(256) void k_mm(const float* __restrict__ Wq,
                                            const float* __restrict__ Wk) {
    int gw = blockIdx.x * 8 + (threadIdx.x >> 5);
    int lane = threadIdx.x & 31;
    int i = gw >> 5;
    int j0 = (gw & 31) * 4;
    float4 qv = ((const float4*)(Wq + i * HD))[lane];
    float p[4];
#pragma unroll
    for (int jj = 0; jj < 4; jj++) {
        float4 kv = ((const float4*)(Wk + (j0 + jj) * HD))[lane];
        p[jj] = qv.x*kv.x + qv.y*kv.y + qv.z*kv.z + qv.w*kv.w;
    }
#pragma unroll
    for (int o = 16; o; o >>= 1) {
#pragma unroll
        for (int jj = 0; jj < 4; jj++)
            p[jj] += __shfl_xor_sync(0xffffffffu, p[jj], o);
    }
    if (lane == 0) {
        g_M[i * HD + j0]     = p[0];
        g_M[i * HD + j0 + 1] = p[1];
        g_M[i * HD + j0 + 2] = p[2];
        g_M[i * HD + j0 + 3] = p[3];
    }
}

// ---------------- a[i] = x_i . u ; b[i] = x_i . v ----------------
__global__ __launch_bounds__(256) void k_ab(const float* __restrict__ x) {
    int w = threadIdx.x >> 5, lane = threadIdx.x & 31;
    int row = blockIdx.x * 8 + w;
    float4 xr = ((const float4*)x)[row * 32 + lane];
    float4 uu = ((const float4*)g_u)[lane];
    float4 vv = ((const float4*)g_v)[lane];
    float pa = xr.x*uu.x + xr.y*uu.y + xr.z*uu.z + xr.w*uu.w;
    float pb = xr.x*vv.x + xr.y*vv.y + xr.z*vv.z + xr.w*vv.w;
#pragma unroll
    for (int o = 16; o; o >>= 1) {
        pa += __shfl_xor_sync(0xffffffffu, pa, o);
        pb += __shfl_xor_sync(0xffffffffu, pb, o);
    }
    if (lane == 0) { g_a[row] = pa; g_b[row] = pb; }
}

// ------- P = x @ M tf32 GEMM, 3-term split, 64x128 tile, DOUBLE-BUFFERED ---
__global__ __launch_bounds__(256) void k_pgemm(const float* __restrict__ x)
{
    __shared__ float Ah[2][16][68], Al[2][16][68];
    __shared__ float Bh[2][16][132], Bl[2][16][132];
    int t = threadIdx.x;
    int row0 = blockIdx.y * 64;
    int wid = t >> 5, lane = t & 31;
    int wm = (wid >> 2) * 32, wn = (wid & 3) * 32;
    int lr = lane & 3, lg = lane >> 2;
    float acc[2][4][4] = {};
    int ar = t >> 2, ak4 = (t & 3) * 4;
    int i0 = t * 2, i1 = t * 2 + 1;
    int bk0 = i0 >> 5, bn0 = (i0 & 31) * 4;
    int bk1 = i1 >> 5, bn1 = (i1 & 31) * 4;

    {
        float4 av = *(const float4*)&x[(row0 + ar) * HD + ak4];
        float hx = f2tf_f(av.x), hy = f2tf_f(av.y), hz = f2tf_f(av.z), hw = f2tf_f(av.w);
        Ah[0][ak4+0][ar] = hx; Al[0][ak4+0][ar] = f2tf_f(av.x - hx);
        Ah[0][ak4+1][ar] = hy; Al[0][ak4+1][ar] = f2tf_f(av.y - hy);
        Ah[0][ak4+2][ar] = hz; Al[0][ak4+2][ar] = f2tf_f(av.z - hz);
        Ah[0][ak4+3][ar] = hw; Al[0][ak4+3][ar] = f2tf_f(av.w - hw);
        float4 bv0 = *(const float4*)&g_M[bk0 * HD + bn0];
        float4 bv1 = *(const float4*)&g_M[bk1 * HD + bn1];
        float4 h, l;
        h.x = f2tf_f(bv0.x); l.x = f2tf_f(bv0.x - h.x);
        h.y = f2tf_f(bv0.y); l.y = f2tf_f(bv0.y - h.y);
        h.z = f2tf_f(bv0.z); l.z = f2tf_f(bv0.z - h.z);
        h.w = f2tf_f(bv0.w); l.w = f2tf_f(bv0.w - h.w);
        *(float4*)&Bh[0][bk0][bn0] = h;
        *(float4*)&Bl[0][bk0][bn0] = l;
        h.x = f2tf_f(bv1.x); l.x = f2tf_f(bv1.x - h.x);
        h.y = f2tf_f(bv1.y); l.y = f2tf_f(bv1.y - h.y);
        h.z = f2tf_f(bv1.z); l.z = f2tf_f(bv1.z - h.z);
        h.w = f2tf_f(bv1.w); l.w = f2tf_f(bv1.w - h.w);
        *(float4*)&Bh[0][bk1][bn1] = h;
        *(float4*)&Bl[0][bk1][bn1] = l;
    }
    __syncthreads();

    for (int it = 0; it < HD / 16; it++) {
        int cur = it & 1, nxt = cur ^ 1;
        float4 aN, bN0, bN1;
        bool more = (it + 1) < HD / 16;
        if (more) {
            int kn = (it + 1) * 16;
            aN  = *(const float4*)&x[(row0 + ar) * HD + kn + ak4];
            bN0 = *(const float4*)&g_M[(kn + bk0) * HD + bn0];
            bN1 = *(const float4*)&g_M[(kn + bk1) * HD + bn1];
        }
#pragma unroll
        for (int ks = 0; ks < 16; ks += 8) {
            unsigned ah[2][4], al[2][4];
#pragma unroll
            for (int mt = 0; mt < 2; mt++) {
                int m = wm + mt * 16 + lg;
                ah[mt][0] = __float_as_uint(Ah[cur][ks + lr][m]);
                ah[mt][1] = __float_as_uint(Ah[cur][ks + lr][m + 8]);
                ah[mt][2] = __float_as_uint(Ah[cur][ks + 4 + lr][m]);
                ah[mt][3] = __float_as_uint(Ah[cur][ks + 4 + lr][m + 8]);
                al[mt][0] = __float_as_uint(Al[cur][ks + lr][m]);
                al[mt][1] = __float_as_uint(Al[cur][ks + lr][m + 8]);
                al[mt][2] = __float_as_uint(Al[cur][ks + 4 + lr][m]);
                al[mt][3] = __float_as_uint(Al[cur][ks + 4 + lr][m + 8]);
            }
#pragma unroll
            for (int nt = 0; nt < 4; nt++) {
                int n = wn + nt * 8 + lg;
                unsigned bh[2], bl[2];
                bh[0] = __float_as_uint(Bh[cur][ks + lr][n]);
                bh[1] = __float_as_uint(Bh[cur][ks + 4 + lr][n]);
                bl[0] = __float_as_uint(Bl[cur][ks + lr][n]);
                bl[1] = __float_as_uint(Bl[cur][ks + 4 + lr][n]);
#pragma unroll
                for (int mt = 0; mt < 2; mt++) {
                    mma_tf32(acc[mt][nt], ah[mt], bl);
                    mma_tf32(acc[mt][nt], al[mt], bh);
                    mma_tf32(acc[mt][nt], ah[mt], bh);
                }
            }
        }
        if (more) {
            float hx = f2tf_f(aN.x), hy = f2tf_f(aN.y), hz = f2tf_f(aN.z), hw = f2tf_f(aN.w);
            Ah[nxt][ak4+0][ar] = hx; Al[nxt][ak4+0][ar] = f2tf_f(aN.x - hx);
            Ah[nxt][ak4+1][ar] = hy; Al[nxt][ak4+1][ar] = f2tf_f(aN.y - hy);
            Ah[nxt][ak4+2][ar] = hz; Al[nxt][ak4+2][ar] = f2tf_f(aN.z - hz);
            Ah[nxt][ak4+3][ar] = hw; Al[nxt][ak4+3][ar] = f2tf_f(aN.w - hw);
            float4 h, l;
            h.x = f2tf_f(bN0.x); l.x = f2tf_f(bN0.x - h.x);
            h.y = f2tf_f(bN0.y); l.y = f2tf_f(bN0.y - h.y);
            h.z = f2tf_f(bN0.z); l.z = f2tf_f(bN0.z - h.z);
            h.w = f2tf_f(bN0.w); l.w = f2tf_f(bN0.w - h.w);
            *(float4*)&Bh[nxt][bk0][bn0] = h;
            *(float4*)&Bl[nxt][bk0][bn0] = l;
            h.x = f2tf_f(bN1.x); l.x = f2tf_f(bN1.x - h.x);
            h.y = f2tf_f(bN1.y); l.y = f2tf_f(bN1.y - h.y);
            h.z = f2tf_f(bN1.z); l.z = f2tf_f(bN1.z - h.z);
            h.w = f2tf_f(bN1.w); l.w = f2tf_f(bN1.w - h.w);
            *(float4*)&Bh[nxt][bk1][bn1] = h;
            *(float4*)&Bl[nxt][bk1][bn1] = l;
        }
        __syncthreads();
    }
#pragma unroll
    for (int mt = 0; mt < 2; mt++)
#pragma unroll
        for (int nt = 0; nt < 4; nt++) {
            int r = row0 + wm + mt * 16 + lg;
            int c = wn + nt * 8 + lr * 2;
#pragma unroll
            for (int h = 0; h < 2; h++) {
                int rr = r + h * 8;
                g_P[rr * HD + c]     = acc[mt][nt][h * 2];
                g_P[rr * HD + c + 1] = acc[mt][nt][h * 2 + 1];
            }
        }
}

// ------- tf32 tensor GEMM: 64x128 tile, DOUBLE-BUFFERED --------------------
// epi: 1 relu, 2 residual*BN, 3 plain residual
__global__ __launch_bounds__(256) void k_mma(
    const float* __restrict__ A, const float* __restrict__ B,
    const float* __restrict__ bias, float* __restrict__ C,
    int Ncols, int K,
    const float* __restrict__ sA, const float* __restrict__ hA,
    int epi, const float* __restrict__ res,
    const float* __restrict__ rs, const float* __restrict__ rh)
{
    __shared__ float As[2][16][68];
    __shared__ float Bs[2][16][132];
    int t = threadIdx.x;
    int row0 = blockIdx.y * 64;
    int col0 = blockIdx.x * 128;
    int wid = t >> 5, lane = t & 31;
    int wm = (wid >> 2) * 32, wn = (wid & 3) * 32;
    int lr = lane & 3, lg = lane >> 2;
    float acc[2][4][4] = {};
    int am_ = t >> 2, ak4 = (t & 3) * 4;
    int i0 = t * 2, i1 = t * 2 + 1;
    int bk0 = i0 >> 5, bn0 = (i0 & 31) * 4;
    int bk1 = i1 >> 5, bn1 = (i1 & 31) * 4;

    {
        float4 av = *(const float4*)&A[(row0 + am_) * K + ak4];
        if (sA) {
            av.x = av.x * sA[ak4  ] + hA[ak4  ];
            av.y = av.y * sA[ak4+1] + hA[ak4+1];
            av.z = av.z * sA[ak4+2] + hA[ak4+2];
            av.w = av.w * sA[ak4+3] + hA[ak4+3];
        }
        As[0][ak4  ][am_] = f2tf_f(av.x);
        As[0][ak4+1][am_] = f2tf_f(av.y);
        As[0][ak4+2][am_] = f2tf_f(av.z);
        As[0][ak4+3][am_] = f2tf_f(av.w);
        float4 bv0 = *(const float4*)&B[bk0 * Ncols + col0 + bn0];
        float4 bv1 = *(const float4*)&B[bk1 * Ncols + col0 + bn1];
        float4 bw;
        bw.x = f2tf_f(bv0.x); bw.y = f2tf_f(bv0.y);
        bw.z = f2tf_f(bv0.z); bw.w = f2tf_f(bv0.w);
        *(float4*)&Bs[0][bk0][bn0] = bw;
        bw.x = f2tf_f(bv1.x); bw.y = f2tf_f(bv1.y);
        bw.z = f2tf_f(bv1.z); bw.w = f2tf_f(bv1.w);
        *(float4*)&Bs[0][bk1][bn1] = bw;
    }
    __syncthreads();

    int T = K / 16;
    for (int it = 0; it < T; it++) {
        int cur = it & 1, nxt = cur ^ 1;
        float4 aN, bN0, bN1;
        bool more = (it + 1) < T;
        int kn = (it + 1) * 16;
        if (more) {
            aN  = *(const float4*)&A[(row0 + am_) * K + kn + ak4];
            bN0 = *(const float4*)&B[(kn + bk0) * Ncols + col0 + bn0];
            bN1 = *(const float4*)&B[(kn + bk1) * Ncols + col0 + bn1];
        }
#pragma unroll
        for (int ks = 0; ks < 16; ks += 8) {
            unsigned a[2][4], b[4][2];
#pragma unroll
            for (int mt = 0; mt < 2; mt++) {
                int m = wm + mt * 16 + lg;
                a[mt][0] = __float_as_uint(As[cur][ks + lr][m]);
                a[mt][1] = __float_as_uint(As[cur][ks + lr][m + 8]);
                a[mt][2] = __float_as_uint(As[cur][ks + 4 + lr][m]);
                a[mt][3] = __float_as_uint(As[cur][ks + 4 + lr][m + 8]);
            }
#pragma unroll
            for (int nt = 0; nt < 4; nt++) {
                int n = wn + nt * 8 + lg;
                b[nt][0] = __float_as_uint(Bs[cur][ks + lr][n]);
                b[nt][1] = __float_as_uint(Bs[cur][ks + 4 + lr][n]);
            }
#pragma unroll
            for (int mt = 0; mt < 2; mt++)
#pragma unroll
                for (int nt = 0; nt < 4; nt++)
                    mma_tf32(acc[mt][nt], a[mt], b[nt]);
        }
        if (more) {
            if (sA) {
                aN.x = aN.x * sA[kn+ak4  ] + hA[kn+ak4  ];
                aN.y = aN.y * sA[kn+ak4+1] + hA[kn+ak4+1];
                aN.z = aN.z * sA[kn+ak4+2] + hA[kn+ak4+2];
                aN.w = aN.w * sA[kn+ak4+3] + hA[kn+ak4+3];
            }
            As[nxt][ak4  ][am_] = f2tf_f(aN.x);
            As[nxt][ak4+1][am_] = f2tf_f(aN.y);
            As[nxt][ak4+2][am_] = f2tf_f(aN.z);
            As[nxt][ak4+3][am_] = f2tf_f(aN.w);
            float4 bw;
            bw.x = f2tf_f(bN0.x); bw.y = f2tf_f(bN0.y);
            bw.z = f2tf_f(bN0.z); bw.w = f2tf_f(bN0.w);
            *(float4*)&Bs[nxt][bk0][bn0] = bw;
            bw.x = f2tf_f(bN1.x); bw.y = f2tf_f(bN1.y);
            bw.z = f2tf_f(bN1.z); bw.w = f2tf_f(bN1.w);
            *(float4*)&Bs[nxt][bk1][bn1] = bw;
        }
        __syncthreads();
    }
#pragma unroll
    for (int mt = 0; mt < 2; mt++) {
#pragma unroll
        for (int nt = 0; nt < 4; nt++) {
            int r = row0 + wm + mt * 16 + lg;
            int c = col0 + wn + nt * 8 + lr * 2;
#pragma unroll
            for (int h = 0; h < 2; h++) {
                int rr = r + h * 8;
                float v0 = acc[mt][nt][h * 2]     + bias[c];
                float v1 = acc[mt][nt][h * 2 + 1] + bias[c + 1];
                if (epi == 1) { v0 = fmaxf(v0, 0.f); v1 = fmaxf(v1, 0.f); }
                else if (epi == 2) {
                    v0 += res[rr * HD + c]     * rs[c]     + rh[c];
                    v1 += res[rr * HD + c + 1] * rs[c + 1] + rh[c + 1];
                } else if (epi == 3) {
                    v0 += res[rr * HD + c];
                    v1 += res[rr * HD + c + 1];
                }
                C[rr * Ncols + c]     = v0;
                C[rr * Ncols + c + 1] = v1;
            }
        }
    }
}

// ---------------- exclusive scan over 16384 counts ----------------
__global__ void k_scan() {
    __shared__ int ps[1024];
    int t = threadIdx.x;
    int base = t * 16;
    int loc[16]; int s = 0;
#pragma unroll
    for (int i = 0; i < 16; i++) { loc[i] = g_hist[base + i]; s += loc[i]; }
    ps[t] = s;
    __syncthreads();
    for (int off = 1; off < 1024; off <<= 1) {
        int v = (t >= off) ? ps[t - off] : 0;
        __syncthreads();
        ps[t] += v;
        __syncthreads();
    }
    int run = ps[t] - s;
#pragma unroll
    for (int i = 0; i < 16; i++) { g_rowstart[base + i] = run; run += loc[i]; }
    if (t == 1023) g_rowstart[NN] = run;
}

// ---------------- column sum of x ----------------
__global__ void k_xsum(const float* __restrict__ x) {
    int c = threadIdx.x;
    int b = blockIdx.x;
    float s = 0.f;
    for (int r = b * 128; r < (b + 1) * 128; r++) s += x[r * HD + c];
    atomicAdd(&g_xsum[c], s);
}

// ------- edge bias + b[dst] + scatter into CSR ----------------
__global__ void k_scatter(const float* __restrict__ ea, const float* __restrict__ We,
                          const float* __restrict__ be, const long long* __restrict__ ei)
{
    int e = blockIdx.x * blockDim.x + threadIdx.x;
    const float4* a4 = (const float4*)(ea + (size_t)e * EDD);
    float s = be[0];
#pragma unroll
    for (int i = 0; i < 4; i++) {
        float4 v = a4[i];
        s += v.x * We[i*4] + v.y * We[i*4+1] + v.z * We[i*4+2] + v.w * We[i*4+3];
    }
    int src = ld_idx(ei, e);
    int dst = ld_idx(ei, EE + e);
    int pos = g_rowstart[src] + atomicAdd(&g_fill[src], 1);
    g_cdst[pos] = dst;
    g_cs[pos]   = s + g_b[dst];
}

// ------- per-row fused score+softmax+x-gather -> y = attn @ x -------------
__global__ __launch_bounds__(256) void k_row(const float* __restrict__ x) {
    __shared__ int   sd[RW][CAP];
    __shared__ float ss[RW][CAP];
    __shared__ int   sf[RW][CAP];
    int t = threadIdx.x;
    int w = t >> 5, lane = t & 31;
    int row = blockIdx.x * RW + w;
    int start = g_rowstart[row], end = g_rowstart[row + 1];
    int k = end - start;
    const float4* X4 = (const float4*)x;
    float4 q = ((const float4*)g_P)[row * 32 + lane];
    float arow = g_a[row] + g_c;
    float4 acc;
    float invden;

    if (k <= CAP) {
        for (int i = lane; i < k; i += 32) { sd[w][i] = g_cdst[start + i]; ss[w][i] = g_cs[start + i]; }
        __syncwarp();
        bool myDup = false;
        for (int i = lane; i < k; i += 32) {
            int d = sd[w][i]; int f = 0;
            while (sd[w][f] != d) f++;
            sf[w][i] = f;
            if (f != i) myDup = true;
        }
        bool anyDup = __any_sync(0xffffffffu, myDup);
        __syncwarp();

        float sumExp = 0.f;
        float4 vs = ((const float4*)g_xsum)[lane];
        float4 a0 = vs, a1 = make_float4(0,0,0,0), a2 = a1, a3 = a1;

        if (!anyDup) {
            for (int i0 = 0; i0 < k; i0 += 4) {
                int n = k - i0; if (n > 4) n = 4;
                int d0 = sd[w][i0];
                int d1 = sd[w][i0 + (n > 1 ? 1 : 0)];
                int d2 = sd[w][i0 + (n > 2 ? 2 : 0)];
                int d3 = sd[w][i0 + (n > 3 ? 3 : 0)];
                float4 x0 = X4[d0 * 32 + lane];
                float4 x1 = X4[d1 * 32 + lane];
                float4 x2 = X4[d2 * 32 + lane];
                float4 x3 = X4[d3 * 32 + lane];
                float p0 = q.x*x0.x + q.y*x0.y + q.z*x0.z + q.w*x0.w;
                float p1 = q.x*x1.x + q.y*x1.y + q.z*x1.z + q.w*x1.w;
                float p2 = q.x*x2.x + q.y*x2.y + q.z*x2.z + q.w*x2.w;
                float p3 = q.x*x3.x + q.y*x3.y + q.z*x3.z + q.w*x3.w;
#pragma unroll
                for (int o = 16; o; o >>= 1) {
                    p0 += __shfl_xor_sync(0xffffffffu, p0, o);
                    p1 += __shfl_xor_sync(0xffffffffu, p1, o);
                    p2 += __shfl_xor_sync(0xffffffffu, p2, o);
                    p3 += __shfl_xor_sync(0xffffffffu, p3, o);
                }
                float s0 = p0 + ss[w][i0] + arow;      s0 = (s0 >= 0.f) ? s0 : NEG * s0;
                float e0 = __expf(s0), w0 = e0 - 1.f;
                float e1 = 0.f, w1 = 0.f, e2 = 0.f, w2 = 0.f, e3 = 0.f, w3 = 0.f;
                if (n > 1) { float s1 = p1 + ss[w][i0+1] + arow; s1 = (s1>=0.f)?s1:NEG*s1; e1 = __expf(s1); w1 = e1 - 1.f; }
                if (n > 2) { float s2 = p2 + ss[w][i0+2] + arow; s2 = (s2>=0.f)?s2:NEG*s2; e2 = __expf(s2); w2 = e2 - 1.f; }
                if (n > 3) { float s3 = p3 + ss[w][i0+3] + arow; s3 = (s3>=0.f)?s3:NEG*s3; e3 = __expf(s3); w3 = e3 - 1.f; }
                sumExp += (e0 + e1) + (e2 + e3);
                a0.x += w0*x0.x; a0.y += w0*x0.y; a0.z += w0*x0.z; a0.w += w0*x0.w;
                a1.x += w1*x1.x; a1.y += w1*x1.y; a1.z += w1*x1.z; a1.w += w1*x1.w;
                a2.x += w2*x2.x; a2.y += w2*x2.y; a2.z += w2*x2.z; a2.w += w2*x2.w;
                a3.x += w3*x3.x; a3.y += w3*x3.y; a3.z += w3*x3.z; a3.w += w3*x3.w;
            }
            invden = 1.f / (sumExp + (float)(NN - k));
        } else {
            for (int i0 = 0; i0 < k; i0 += 4) {
                int n = k - i0; if (n > 4) n = 4;
                int d0 = sd[w][i0];
                int d1 = sd[w][i0 + (n > 1 ? 1 : 0)];
                int d2 = sd[w][i0 + (n > 2 ? 2 : 0)];
                int d3 = sd[w][i0 + (n > 3 ? 3 : 0)];
                float4 x0 = X4[d0 * 32 + lane];
                float4 x1 = X4[d1 * 32 + lane];
                float4 x2 = X4[d2 * 32 + lane];
                float4 x3 = X4[d3 * 32 + lane];
                float p0 = q.x*x0.x + q.y*x0.y + q.z*x0.z + q.w*x0.w;
                float p1 = q.x*x1.x + q.y*x1.y + q.z*x1.z + q.w*x1.w;
                float p2 = q.x*x2.x + q.y*x2.y + q.z*x2.z + q.w*x2.w;
                float p3 = q.x*x3.x + q.y*x3.y + q.z*x3.z + q.w*x3.w;
#pragma unroll
                for (int o = 16; o; o >>= 1) {
                    p0 += __shfl_xor_sync(0xffffffffu, p0, o);
                    p1 += __shfl_xor_sync(0xffffffffu, p1, o);
                    p2 += __shfl_xor_sync(0xffffffffu, p2, o);
                    p3 += __shfl_xor_sync(0xffffffffu, p3, o);
                }
                if (lane == 0) {
                    float s0 = p0 + ss[w][i0] + arow; ss[w][i0] = (s0>=0.f)?s0:NEG*s0;
                    if (n > 1) { float s1 = p1 + ss[w][i0+1] + arow; ss[w][i0+1] = (s1>=0.f)?s1:NEG*s1; }
                    if (n > 2) { float s2 = p2 + ss[w][i0+2] + arow; ss[w][i0+2] = (s2>=0.f)?s2:NEG*s2; }
                    if (n > 3) { float s3 = p3 + ss[w][i0+3] + arow; ss[w][i0+3] = (s3>=0.f)?s3:NEG*s3; }
                }
            }
            __syncwarp();
            for (int i = lane; i < k; i += 32)
                if (sf[w][i] != i) atomicAdd(&ss[w][sf[w][i]], ss[w][i]);
            __syncwarp();
            int cnt = 0;
            for (int i = lane; i < k; i += 32) {
                float wv = 0.f;
                if (sf[w][i] == i) {
                    float e1 = __expf(ss[w][i]);
                    sumExp += e1;
                    wv = e1 - 1.f;
                    cnt++;
                }
                ss[w][i] = wv;
            }
            __syncwarp();
            cnt = redux_addi(cnt);
            sumExp = wsum32(sumExp);
            for (int i = 0; i + 4 <= k; i += 4) {
                float w0 = ss[w][i], w1 = ss[w][i+1], w2 = ss[w][i+2], w3 = ss[w][i+3];
                float4 v0 = X4[sd[w][i]   * 32 + lane];
                float4 v1 = X4[sd[w][i+1] * 32 + lane];
                float4 v2 = X4[sd[w][i+2] * 32 + lane];
                float4 v3 = X4[sd[w][i+3] * 32 + lane];
                a0.x += w0*v0.x; a0.y += w0*v0.y; a0.z += w0*v0.z; a0.w += w0*v0.w;
                a1.x += w1*v1.x; a1.y += w1*v1.y; a1.z += w1*v1.z; a1.w += w1*v1.w;
                a2.x += w2*v2.x; a2.y += w2*v2.y; a2.z += w2*v2.z; a2.w += w2*v2.w;
                a3.x += w3*v3.x; a3.y += w3*v3.y; a3.z += w3*v3.z; a3.w += w3*v3.w;
            }
            for (int i = k & ~3; i < k; i++) {
                float wv = ss[w][i];
                float4 v = X4[sd[w][i] * 32 + lane];
                a0.x += wv*v.x; a0.y += wv*v.y; a0.z += wv*v.z; a0.w += wv*v.w;
            }
            invden = 1.f / (sumExp + (float)(NN - cnt));
        }
        acc.x = (a0.x + a1.x) + (a2.x + a3.x);
        acc.y = (a0.y + a1.y) + (a2.y + a3.y);
        acc.z = (a0.z + a1.z) + (a2.z + a3.z);
        acc.w = (a0.w + a1.w) + (a2.w + a3.w);
    } else {
        float sumExp = 0.f; int cnt = 0;
        float4 vs = ((const float4*)g_xsum)[lane];
        acc.x = vs.x; acc.y = vs.y; acc.z = vs.z; acc.w = vs.w;
        for (int i = 0; i < k; i++) {
            int d = g_cdst[start + i];
            bool first = true;
            for (int j = 0; j < i; j++) if (g_cdst[start + j] == d) { first = false; break; }
            if (!first) continue;
            float4 xv = X4[d * 32 + lane];
            float p = wsum32(q.x*xv.x + q.y*xv.y + q.z*xv.z + q.w*xv.w);
            float v = 0.f;
            for (int j = i; j < k; j++)
                if (g_cdst[start + j] == d) {
                    float s = p + g_cs[start + j] + arow;
                    v += (s >= 0.f) ? s : NEG * s;
                }
            float e1 = __expf(v);
            sumExp += e1;
            float wv = e1 - 1.f;
            cnt++;
            acc.x += wv*xv.x; acc.y += wv*xv.y; acc.z += wv*xv.z; acc.w += wv*xv.w;
        }
        invden = 1.f / (sumExp + (float)(NN - cnt));
    }

    float4 o;
    o.x = acc.x * invden;
    o.y = acc.y * invden;
    o.z = acc.z * invden;
    o.w = acc.w * invden;
    ((float4*)g_y)[row * 32 + lane] = o;
}

// ---------------- batchnorm column stats ----------------
__global__ void k_stats(const float* __restrict__ src, float* __restrict__ osum, float* __restrict__ osq) {
    __shared__ float sh1[128], sh2[128];
    int t = threadIdx.x;
    int c = t & 127, half = t >> 7;
    int r0 = blockIdx.x * 128 + half;
    float s = 0.f, q = 0.f;
    for (int i = 0; i < 64; i++) {
        float v = src[(r0 + 2 * i) * HD + c];
        s += v; q += v * v;
    }
    if (half) { sh1[c] = s; sh2[c] = q; }
    __syncthreads();
    if (!half) {
        atomicAdd(&osum[c], s + sh1[c]);
        atomicAdd(&osq[c],  q + sh2[c]);
    }
}

__global__ void k_finalize(const float* __restrict__ sum, const float* __restrict__ sq,
                           const float* __restrict__ g, const float* __restrict__ b,
                           float* __restrict__ sc, float* __restrict__ sh) {
    int c = threadIdx.x;
    float mean = sum[c] * (1.f / NN);
    float var  = sq[c] * (1.f / NN) - mean * mean;
    float s = g[c] * rsqrtf(var + EPSB);
    sc[c] = s;
    sh[c] = b[c] - mean * s;
}

// ---------------- final BN2 apply ----------------
__global__ void k_out(float* __restrict__ out) {
    int i = blockIdx.x * blockDim.x + threadIdx.x;
    float4 v = ((const float4*)g_h2)[i];
    int c = (i & 31) * 4;
    float4 o;
    o.x = v.x * g_scale2[c  ] + g_shift2[c  ];
    o.y = v.y * g_scale2[c+1] + g_shift2[c+1];
    o.z = v.z * g_scale2[c+2] + g_shift2[c+2];
    o.w = v.w * g_scale2[c+3] + g_shift2[c+3];
    ((float4*)out)[i] = o;
}

// ---------------- host ----------------
extern "C" void kernel_launch(void* const* d_in, const int* in_sizes, int n_in,
                              void* d_out, int out_size) {
    const float*     x   = (const float*)d_in[0];
    const long long* ei  = (const long long*)d_in[1];
    const float*     ea  = (const float*)d_in[2];
    const float*     Wq  = (const float*)d_in[3];  const float* bq  = (const float*)d_in[4];
    const float*     Wk  = (const float*)d_in[5];  const float* bk  = (const float*)d_in[6];
    const float*     Wv  = (const float*)d_in[7];  const float* bv  = (const float*)d_in[8];
    const float*     We  = (const float*)d_in[9];  const float* be  = (const float*)d_in[10];
    const float*     g1  = (const float*)d_in[11]; const float* be1 = (const float*)d_in[12];
    const float*     W1  = (const float*)d_in[13]; const float* b1  = (const float*)d_in[14];
    const float*     W2  = (const float*)d_in[15]; const float* b2  = (const float*)d_in[16];
    const float*     g2  = (const float*)d_in[17]; const float* be2 = (const float*)d_in[18];

    float *py, *ph0, *pf1, *ph2;
    float *ps1, *pq1, *psc1, *psh1, *ps2, *pq2, *psc2, *psh2;
    cudaGetSymbolAddress((void**)&py,   g_y);
    cudaGetSymbolAddress((void**)&ph0,  g_h0);
    cudaGetSymbolAddress((void**)&pf1,  g_f1);
    cudaGetSymbolAddress((void**)&ph2,  g_h2);
    cudaGetSymbolAddress((void**)&ps1,  g_sum1);
    cudaGetSymbolAddress((void**)&pq1,  g_sq1);
    cudaGetSymbolAddress((void**)&psc1, g_scale1);
    cudaGetSymbolAddress((void**)&psh1, g_shift1);
    cudaGetSymbolAddress((void**)&ps2,  g_sum2);
    cudaGetSymbolAddress((void**)&pq2,  g_sq2);
    cudaGetSymbolAddress((void**)&psc2, g_scale2);
    cudaGetSymbolAddress((void**)&psh2, g_shift2);

    static cudaStream_t s2 = nullptr;
    static cudaEvent_t evFork = nullptr, evJoin = nullptr;
    if (s2 == nullptr) {
        cudaStreamCreateWithFlags(&s2, cudaStreamNonBlocking);
        cudaEventCreateWithFlags(&evFork, cudaEventDisableTiming);
        cudaEventCreateWithFlags(&evJoin, cudaEventDisableTiming);
    }

    cudaEventRecord(evFork, 0);
    cudaStreamWaitEvent(s2, evFork, 0);

    k_uvc<<<32, 256, 0, s2>>>(Wq, bk, Wk, bq);
    k_ab<<<NN / 8, 256, 0, s2>>>(x);
    k_mm<<<512, 256, 0, s2>>>(Wq, Wk);
    dim3 gP(1, NN / 64);
    k_pgemm<<<gP, 256, 0, s2>>>(x);
    k_xsum<<<128, 128, 0, s2>>>(x);
    cudaEventRecord(evJoin, s2);

    k_init<<<EE / 256, 256>>>(ei);
    k_hist<<<EE / 256, 256>>>(ei);
    k_scan<<<1, 1024>>>();

    cudaStreamWaitEvent(0, evJoin, 0);

    k_scatter<<<EE / 256, 256>>>(ea, We, be, ei);
    k_row<<<NN / RW, 256>>>(x);

    dim3 gY(HD / 128, NN / 64);
    k_mma<<<gY, 256>>>(py, Wv, bv, ph0, HD, HD, nullptr, nullptr, 3, x, nullptr, nullptr);

    k_stats<<<128, 256>>>(ph0, ps1, pq1);
    k_finalize<<<1, 128>>>(ps1, pq1, g1, be1, psc1, psh1);

    dim3 gF1(HID / 128, NN / 64);
    k_mma<<<gF1, 256>>>(ph0, W1, b1, pf1, HID, HD, psc1, psh1, 1, nullptr, nullptr, nullptr);
    dim3 gF2(HD / 128, NN / 64);
    k_mma<<<gF2, 256>>>(pf1, W2, b2, ph2, HD, HID, nullptr, nullptr, 2, ph0, psc1, psh1);

    k_stats<<<128, 256>>>(ph2, ps2, pq2);
    k_finalize<<<1, 128>>>(ps2, pq2, g2, be2, psc2, psh2);
    k_out<<<(NN * HD / 4) / 256, 256>>>((float*)d_out);
}